// round 1
// baseline (speedup 1.0000x reference)
#include <cuda_runtime.h>
#include <cuda_bf16.h>
#include <cstdint>

// Problem constants
#define BB 4
#define SS 1024
#define DD 1024
#define HH 16
#define DK 64
#define DV 64

// Scratch (device globals -- allowed; no cudaMalloc)
__device__ float g_q  [BB*HH*SS*DK];   // [b,h,s,d]
__device__ float g_k  [BB*HH*SS*DK];   // [b,h,s,d]
__device__ float g_vt [BB*HH*DV*SS];   // [b,h,d,s]  (V transposed)
__device__ float g_ctx[BB*SS*HH*DV];   // [b,s,h*d]
__device__ float g_scores[(size_t)BB*HH*SS*SS]; // [b*h, q, k]  256 MB

__device__ __forceinline__ uint32_t f2tf(float f) {
    uint32_t u;
    asm("cvt.rna.tf32.f32 %0, %1;" : "=r"(u) : "f"(f));
    return u;
}

__device__ __forceinline__ void mma_tf32(float c[4], const uint32_t a[4], const uint32_t b[2]) {
    asm volatile(
        "mma.sync.aligned.m16n8k8.row.col.f32.tf32.tf32.f32 "
        "{%0,%1,%2,%3}, {%4,%5,%6,%7}, {%8,%9}, {%0,%1,%2,%3};"
        : "+f"(c[0]), "+f"(c[1]), "+f"(c[2]), "+f"(c[3])
        : "r"(a[0]), "r"(a[1]), "r"(a[2]), "r"(a[3]),
          "r"(b[0]), "r"(b[1]));
}

// Epilogue store dispatch.
// MODE 0: plain row-major C[M,N]
// MODE 1: q/k proj scatter -> [b,h,s,d]
// MODE 2: v  proj scatter  -> [b,h,d,s]  (transposed V)
// MODE 3: scores: C = acc*scale + bias[b,q,k], batched z=(b*H+h)
// MODE 4: ctx scatter: batch z=(b,h), C[s, d] -> ctx[(b*S+s)*1024 + h*64 + d]
template<int MODE>
__device__ __forceinline__ void store_c(float* __restrict__ C, const float* __restrict__ bias,
                                        int z, int m, int n, int N, float scale, float v) {
    if constexpr (MODE == 0) {
        C[(size_t)m * N + n] = v;
    } else if constexpr (MODE == 1) {
        int b = m >> 10, s = m & 1023;
        int h = n >> 6,  d = n & 63;
        C[(((size_t)(b * HH + h)) * SS + s) * DK + d] = v;
    } else if constexpr (MODE == 2) {
        int b = m >> 10, s = m & 1023;
        int h = n >> 6,  d = n & 63;
        C[(((size_t)(b * HH + h)) * DV + d) * SS + s] = v;
    } else if constexpr (MODE == 3) {
        int b = z >> 4; // z = b*H + h
        size_t off = (size_t)z * SS * SS + (size_t)m * SS + n;
        C[off] = v * scale + bias[(size_t)b * SS * SS + (size_t)m * SS + n];
    } else if constexpr (MODE == 4) {
        int b = z >> 4, h = z & 15;
        C[((size_t)(b * SS + m)) * (HH * DV) + h * DV + n] = v;
    }
}

// Generic NT GEMM: C = A[M,K] * Bm[N,K]^T  (both row-major, K-contiguous).
// tf32 mma.sync, fp32 accumulate. BK fixed at 32. Dims must divide tiles.
template<int BM, int BN, int BK, int WM, int WN, int MODE>
__global__ __launch_bounds__(256)
void gemm_tf32(const float* __restrict__ A, const float* __restrict__ Bm,
               float* __restrict__ C, const float* __restrict__ bias,
               int M, int N, int K, long sA, long sB, float scale) {
    static_assert(BK == 32, "");
    static_assert(WM * WN == 8, "");
    constexpr int TM = BM / WM, TN = BN / WN;
    constexpr int MI = TM / 16, NJ = TN / 8;
    constexpr int LDS_ = BK + 4; // 36 floats: conflict-free fragment loads

    const int z = blockIdx.z;
    A  += (size_t)z * sA;
    Bm += (size_t)z * sB;

    __shared__ float As[BM * LDS_];
    __shared__ float Bs[BN * LDS_];

    const int tid = threadIdx.x;
    const int w = tid >> 5, lane = tid & 31;
    const int g = lane >> 2, t = lane & 3;
    const int wm = w % WM, wn = w / WM;
    const int m_blk = blockIdx.y * BM, n_blk = blockIdx.x * BN;

    float acc[MI][NJ][4];
    #pragma unroll
    for (int i = 0; i < MI; i++)
        #pragma unroll
        for (int j = 0; j < NJ; j++)
            #pragma unroll
            for (int c = 0; c < 4; c++) acc[i][j][c] = 0.f;

    constexpr int A_LD = BM * BK / 4 / 256; // float4 per thread
    constexpr int B_LD = BN * BK / 4 / 256;

    for (int kt = 0; kt < K; kt += BK) {
        #pragma unroll
        for (int i = 0; i < A_LD; i++) {
            int idx = tid + i * 256;
            int r = idx >> 3, c4 = idx & 7; // BK/4 = 8 float4 per row
            float4 v = *reinterpret_cast<const float4*>(&A[(size_t)(m_blk + r) * K + kt + c4 * 4]);
            *reinterpret_cast<float4*>(&As[r * LDS_ + c4 * 4]) = v;
        }
        #pragma unroll
        for (int i = 0; i < B_LD; i++) {
            int idx = tid + i * 256;
            int r = idx >> 3, c4 = idx & 7;
            float4 v = *reinterpret_cast<const float4*>(&Bm[(size_t)(n_blk + r) * K + kt + c4 * 4]);
            *reinterpret_cast<float4*>(&Bs[r * LDS_ + c4 * 4]) = v;
        }
        __syncthreads();

        #pragma unroll
        for (int kk = 0; kk < BK; kk += 8) {
            uint32_t a[MI][4], b[NJ][2];
            #pragma unroll
            for (int i = 0; i < MI; i++) {
                int bm = wm * TM + i * 16;
                a[i][0] = f2tf(As[(bm + g)     * LDS_ + kk + t]);
                a[i][1] = f2tf(As[(bm + g + 8) * LDS_ + kk + t]);
                a[i][2] = f2tf(As[(bm + g)     * LDS_ + kk + t + 4]);
                a[i][3] = f2tf(As[(bm + g + 8) * LDS_ + kk + t + 4]);
            }
            #pragma unroll
            for (int j = 0; j < NJ; j++) {
                int bn = wn * TN + j * 8;
                b[j][0] = f2tf(Bs[(bn + g) * LDS_ + kk + t]);
                b[j][1] = f2tf(Bs[(bn + g) * LDS_ + kk + t + 4]);
            }
            #pragma unroll
            for (int i = 0; i < MI; i++)
                #pragma unroll
                for (int j = 0; j < NJ; j++)
                    mma_tf32(acc[i][j], a[i], b[j]);
        }
        __syncthreads();
    }

    // Epilogue
    #pragma unroll
    for (int i = 0; i < MI; i++) {
        #pragma unroll
        for (int j = 0; j < NJ; j++) {
            int m0 = m_blk + wm * TM + i * 16 + g;
            int n0 = n_blk + wn * TN + j * 8 + 2 * t;
            store_c<MODE>(C, bias, z, m0,     n0,     N, scale, acc[i][j][0]);
            store_c<MODE>(C, bias, z, m0,     n0 + 1, N, scale, acc[i][j][1]);
            store_c<MODE>(C, bias, z, m0 + 8, n0,     N, scale, acc[i][j][2]);
            store_c<MODE>(C, bias, z, m0 + 8, n0 + 1, N, scale, acc[i][j][3]);
        }
    }
}

// Row softmax over 1024-wide rows, numerically stable, in place.
__global__ __launch_bounds__(256)
void softmax_rows(float* __restrict__ P) {
    const size_t row = blockIdx.x;
    float* p = P + row * 1024;
    const int tid = threadIdx.x;
    float4 v = reinterpret_cast<float4*>(p)[tid];

    float mx = fmaxf(fmaxf(v.x, v.y), fmaxf(v.z, v.w));
    #pragma unroll
    for (int o = 16; o; o >>= 1) mx = fmaxf(mx, __shfl_xor_sync(0xffffffffu, mx, o));

    __shared__ float red[8];
    __shared__ float s_bcast;
    const int w = tid >> 5, lane = tid & 31;
    if (lane == 0) red[w] = mx;
    __syncthreads();
    if (tid == 0) {
        float m = red[0];
        #pragma unroll
        for (int i = 1; i < 8; i++) m = fmaxf(m, red[i]);
        s_bcast = m;
    }
    __syncthreads();
    mx = s_bcast;

    v.x = expf(v.x - mx); v.y = expf(v.y - mx);
    v.z = expf(v.z - mx); v.w = expf(v.w - mx);
    float sum = v.x + v.y + v.z + v.w;
    #pragma unroll
    for (int o = 16; o; o >>= 1) sum += __shfl_xor_sync(0xffffffffu, sum, o);
    __syncthreads(); // protect red[] reuse
    if (lane == 0) red[w] = sum;
    __syncthreads();
    if (tid == 0) {
        float s = 0.f;
        #pragma unroll
        for (int i = 0; i < 8; i++) s += red[i];
        s_bcast = 1.f / s;
    }
    __syncthreads();
    float inv = s_bcast;
    v.x *= inv; v.y *= inv; v.z *= inv; v.w *= inv;
    reinterpret_cast<float4*>(p)[tid] = v;
}

extern "C" void kernel_launch(void* const* d_in, const int* in_sizes, int n_in,
                              void* d_out, int out_size) {
    const float* queries = (const float*)d_in[0];
    const float* keys    = (const float*)d_in[1];
    const float* values  = (const float*)d_in[2];
    const float* bias    = (const float*)d_in[3];
    const float* Wq      = (const float*)d_in[4];
    const float* Wk      = (const float*)d_in[5];
    const float* Wv      = (const float*)d_in[6];
    const float* Wp      = (const float*)d_in[7];
    float* out = (float*)d_out;

    float *q, *k, *vt, *ctx, *sc;
    cudaGetSymbolAddress((void**)&q,   g_q);
    cudaGetSymbolAddress((void**)&k,   g_k);
    cudaGetSymbolAddress((void**)&vt,  g_vt);
    cudaGetSymbolAddress((void**)&ctx, g_ctx);
    cudaGetSymbolAddress((void**)&sc,  g_scores);

    const int M = BB * SS;       // 4096
    const float inv_sqrt_d = 0.03125f; // 1024^-0.5

    // Projections: X[4096,1024] @ W[1024,1024]^T
    gemm_tf32<128,128,32,2,4,1><<<dim3(8, 32, 1), 256>>>(queries, Wq, q,  nullptr, M, 1024, 1024, 0, 0, 1.f);
    gemm_tf32<128,128,32,2,4,1><<<dim3(8, 32, 1), 256>>>(keys,    Wk, k,  nullptr, M, 1024, 1024, 0, 0, 1.f);
    gemm_tf32<128,128,32,2,4,2><<<dim3(8, 32, 1), 256>>>(values,  Wv, vt, nullptr, M, 1024, 1024, 0, 0, 1.f);

    // Scores: per (b,h): Q[S,64] @ K[S,64]^T * scale + bias
    gemm_tf32<128,128,32,2,4,3><<<dim3(8, 8, BB*HH), 256>>>(q, k, sc, bias,
        SS, SS, DK, (long)SS*DK, (long)SS*DK, inv_sqrt_d);

    // Softmax over all B*H*S rows
    softmax_rows<<<BB*HH*SS, 256>>>(sc);

    // Ctx: per (b,h): P[S,S] @ Vt[64,S]^T -> ctx[b,s,h*64+d]
    gemm_tf32<128,64,32,4,2,4><<<dim3(1, 8, BB*HH), 256>>>(sc, vt, ctx, nullptr,
        SS, DV, SS, (long)SS*SS, (long)DV*SS, 1.f);

    // Output projection: ctx[4096,1024] @ Wp[1024,1024]^T
    gemm_tf32<128,128,32,2,4,0><<<dim3(8, 32, 1), 256>>>(ctx, Wp, out, nullptr, M, 1024, 1024, 0, 0, 1.f);
}

// round 2
// speedup vs baseline: 1.4678x; 1.4678x over previous
#include <cuda_runtime.h>
#include <cuda_bf16.h>
#include <cstdint>

// Problem constants
#define BB 4
#define SS 1024
#define DD 1024
#define HH 16
#define DK 64
#define DV 64

// Scratch (device globals -- allowed; no cudaMalloc)
__device__ float g_q  [BB*HH*SS*DK];   // [b,h,s,d]
__device__ float g_k  [BB*HH*SS*DK];   // [b,h,s,d]
__device__ float g_vt [BB*HH*DV*SS];   // [b,h,d,s]  (V transposed)
__device__ float g_ctx[BB*SS*HH*DV];   // [b,s,h*d]

__device__ __forceinline__ uint32_t f2tf(float f) {
    uint32_t u;
    asm("cvt.rna.tf32.f32 %0, %1;" : "=r"(u) : "f"(f));
    return u;
}

__device__ __forceinline__ void mma_tf32(float c[4], const uint32_t a[4], const uint32_t b[2]) {
    asm volatile(
        "mma.sync.aligned.m16n8k8.row.col.f32.tf32.tf32.f32 "
        "{%0,%1,%2,%3}, {%4,%5,%6,%7}, {%8,%9}, {%0,%1,%2,%3};"
        : "+f"(c[0]), "+f"(c[1]), "+f"(c[2]), "+f"(c[3])
        : "r"(a[0]), "r"(a[1]), "r"(a[2]), "r"(a[3]),
          "r"(b[0]), "r"(b[1]));
}

// Epilogue store dispatch.
// MODE 0: plain row-major C[M,N]
// MODE 1: q/k proj scatter -> [b,h,s,d]
// MODE 2: v  proj scatter  -> [b,h,d,s]  (transposed V)
template<int MODE>
__device__ __forceinline__ void store_c(float* __restrict__ C,
                                        int m, int n, int N, float v) {
    if constexpr (MODE == 0) {
        C[(size_t)m * N + n] = v;
    } else if constexpr (MODE == 1) {
        int b = m >> 10, s = m & 1023;
        int h = n >> 6,  d = n & 63;
        C[(((size_t)(b * HH + h)) * SS + s) * DK + d] = v;
    } else if constexpr (MODE == 2) {
        int b = m >> 10, s = m & 1023;
        int h = n >> 6,  d = n & 63;
        C[(((size_t)(b * HH + h)) * DV + d) * SS + s] = v;
    }
}

// Generic NT GEMM: C = A[M,K] * Bm[N,K]^T  (both row-major, K-contiguous).
// tf32 mma.sync, fp32 accumulate. smem holds pre-converted tf32 bits.
template<int BM, int BN, int BK, int WM, int WN, int MODE>
__global__ __launch_bounds__(256)
void gemm_tf32(const float* __restrict__ A, const float* __restrict__ Bm,
               float* __restrict__ C, int M, int N, int K) {
    static_assert(BK == 32, "");
    static_assert(WM * WN == 8, "");
    constexpr int TM = BM / WM, TN = BN / WN;
    constexpr int MI = TM / 16, NJ = TN / 8;
    constexpr int LDS_ = BK + 4; // 36: conflict-free fragment loads

    __shared__ uint32_t As[BM * LDS_];
    __shared__ uint32_t Bs[BN * LDS_];

    const int tid = threadIdx.x;
    const int w = tid >> 5, lane = tid & 31;
    const int g = lane >> 2, t = lane & 3;
    const int wm = w % WM, wn = w / WM;
    const int m_blk = blockIdx.y * BM, n_blk = blockIdx.x * BN;

    float acc[MI][NJ][4];
    #pragma unroll
    for (int i = 0; i < MI; i++)
        #pragma unroll
        for (int j = 0; j < NJ; j++)
            #pragma unroll
            for (int c = 0; c < 4; c++) acc[i][j][c] = 0.f;

    constexpr int A_LD = BM * BK / 4 / 256;
    constexpr int B_LD = BN * BK / 4 / 256;

    for (int kt = 0; kt < K; kt += BK) {
        #pragma unroll
        for (int i = 0; i < A_LD; i++) {
            int idx = tid + i * 256;
            int r = idx >> 3, c4 = idx & 7;
            float4 v = *reinterpret_cast<const float4*>(&A[(size_t)(m_blk + r) * K + kt + c4 * 4]);
            uint4 u = make_uint4(f2tf(v.x), f2tf(v.y), f2tf(v.z), f2tf(v.w));
            *reinterpret_cast<uint4*>(&As[r * LDS_ + c4 * 4]) = u;
        }
        #pragma unroll
        for (int i = 0; i < B_LD; i++) {
            int idx = tid + i * 256;
            int r = idx >> 3, c4 = idx & 7;
            float4 v = *reinterpret_cast<const float4*>(&Bm[(size_t)(n_blk + r) * K + kt + c4 * 4]);
            uint4 u = make_uint4(f2tf(v.x), f2tf(v.y), f2tf(v.z), f2tf(v.w));
            *reinterpret_cast<uint4*>(&Bs[r * LDS_ + c4 * 4]) = u;
        }
        __syncthreads();

        #pragma unroll
        for (int kk = 0; kk < BK; kk += 8) {
            uint32_t a[MI][4], b[NJ][2];
            #pragma unroll
            for (int i = 0; i < MI; i++) {
                int bm = wm * TM + i * 16;
                a[i][0] = As[(bm + g)     * LDS_ + kk + t];
                a[i][1] = As[(bm + g + 8) * LDS_ + kk + t];
                a[i][2] = As[(bm + g)     * LDS_ + kk + t + 4];
                a[i][3] = As[(bm + g + 8) * LDS_ + kk + t + 4];
            }
            #pragma unroll
            for (int j = 0; j < NJ; j++) {
                int bn = wn * TN + j * 8;
                b[j][0] = Bs[(bn + g) * LDS_ + kk + t];
                b[j][1] = Bs[(bn + g) * LDS_ + kk + t + 4];
            }
            #pragma unroll
            for (int i = 0; i < MI; i++)
                #pragma unroll
                for (int j = 0; j < NJ; j++)
                    mma_tf32(acc[i][j], a[i], b[j]);
        }
        __syncthreads();
    }

    #pragma unroll
    for (int i = 0; i < MI; i++) {
        #pragma unroll
        for (int j = 0; j < NJ; j++) {
            int m0 = m_blk + wm * TM + i * 16 + g;
            int n0 = n_blk + wn * TN + j * 8 + 2 * t;
            store_c<MODE>(C, m0,     n0,     N, acc[i][j][0]);
            store_c<MODE>(C, m0,     n0 + 1, N, acc[i][j][1]);
            store_c<MODE>(C, m0 + 8, n0,     N, acc[i][j][2]);
            store_c<MODE>(C, m0 + 8, n0 + 1, N, acc[i][j][3]);
        }
    }
}

// ---------------------------------------------------------------------------
// Fused flash attention: per CTA = (128 queries) x one (b,h).
// S = Q*K^T*scale + bias, online softmax, O += P*V. 8 warps, each owns 16 rows.
// ---------------------------------------------------------------------------
#define KS_LD 68   // 64 + 4 pad (stride mod 32 == 4 -> conflict-free frags)
#define VS_LD 132  // 128 + 4 pad

__global__ __launch_bounds__(256)
void flash_attn(const float* __restrict__ Q, const float* __restrict__ K,
                const float* __restrict__ Vt, const float* __restrict__ bias,
                float* __restrict__ ctx) {
    extern __shared__ uint32_t dsm[];
    uint32_t* Ks = dsm;                // [128][KS_LD] tf32
    uint32_t* Vs = dsm + 128 * KS_LD;  // [64][VS_LD] tf32

    const int z = blockIdx.y;            // b*H + h
    const int q0 = blockIdx.x * 128;
    const int b = z >> 4, h = z & 15;
    const int tid = threadIdx.x, w = tid >> 5, lane = tid & 31;
    const int g = lane >> 2, t = lane & 3;
    const size_t zoff = (size_t)z * SS * 64;
    const float* bias_b = bias + (size_t)b * SS * SS;
    const float scale = 0.03125f; // D^-0.5

    // Q fragments (persistent, tf32)
    uint32_t qf[8][4];
    {
        const float* qp = Q + zoff + (size_t)(q0 + w * 16) * 64;
        #pragma unroll
        for (int s = 0; s < 8; s++) {
            qf[s][0] = f2tf(qp[(size_t)g       * 64 + 8 * s + t]);
            qf[s][1] = f2tf(qp[(size_t)(g + 8) * 64 + 8 * s + t]);
            qf[s][2] = f2tf(qp[(size_t)g       * 64 + 8 * s + t + 4]);
            qf[s][3] = f2tf(qp[(size_t)(g + 8) * 64 + 8 * s + t + 4]);
        }
    }

    float oacc[8][4];
    #pragma unroll
    for (int n = 0; n < 8; n++)
        #pragma unroll
        for (int c = 0; c < 4; c++) oacc[n][c] = 0.f;

    float mrun0 = -1e30f, mrun1 = -1e30f, l0 = 0.f, l1 = 0.f;
    const int rowg = q0 + w * 16 + g;

    const int s0l = (lane & 28) | (t >> 1);        // src lane for cols t
    const int s1l = (lane & 28) | (2 + (t >> 1));  // src lane for cols t+4
    const bool odd = t & 1;

    for (int kt = 0; kt < 8; kt++) {
        const int kb = kt * 128;
        __syncthreads();
        // K tile [128 keys][64 dk] -> tf32 smem
        #pragma unroll
        for (int i = 0; i < 8; i++) {
            int idx = tid + i * 256;
            int r = idx >> 4, c = (idx & 15) * 4;
            float4 v = *reinterpret_cast<const float4*>(&K[zoff + (size_t)(kb + r) * 64 + c]);
            *reinterpret_cast<uint4*>(&Ks[r * KS_LD + c]) =
                make_uint4(f2tf(v.x), f2tf(v.y), f2tf(v.z), f2tf(v.w));
        }
        // Vt tile [64 d][128 keys] -> tf32 smem
        #pragma unroll
        for (int i = 0; i < 8; i++) {
            int idx = tid + i * 256;
            int r = idx >> 5, c = (idx & 31) * 4;
            float4 v = *reinterpret_cast<const float4*>(&Vt[zoff + (size_t)r * 1024 + kb + c]);
            *reinterpret_cast<uint4*>(&Vs[r * VS_LD + c]) =
                make_uint4(f2tf(v.x), f2tf(v.y), f2tf(v.z), f2tf(v.w));
        }
        __syncthreads();

        // S = Q K^T * scale + bias
        float sacc[16][4];
        float tm0 = -1e30f, tm1 = -1e30f;
        #pragma unroll
        for (int j = 0; j < 16; j++) {
            float c4[4] = {0.f, 0.f, 0.f, 0.f};
            #pragma unroll
            for (int kk = 0; kk < 8; kk++) {
                uint32_t bb[2] = { Ks[(8 * j + g) * KS_LD + 8 * kk + t],
                                   Ks[(8 * j + g) * KS_LD + 8 * kk + t + 4] };
                mma_tf32(c4, qf[kk], bb);
            }
            float2 b0v = *reinterpret_cast<const float2*>(
                &bias_b[(size_t)rowg * SS + kb + 8 * j + 2 * t]);
            float2 b1v = *reinterpret_cast<const float2*>(
                &bias_b[(size_t)(rowg + 8) * SS + kb + 8 * j + 2 * t]);
            sacc[j][0] = fmaf(c4[0], scale, b0v.x);
            sacc[j][1] = fmaf(c4[1], scale, b0v.y);
            sacc[j][2] = fmaf(c4[2], scale, b1v.x);
            sacc[j][3] = fmaf(c4[3], scale, b1v.y);
            tm0 = fmaxf(tm0, fmaxf(sacc[j][0], sacc[j][1]));
            tm1 = fmaxf(tm1, fmaxf(sacc[j][2], sacc[j][3]));
        }
        tm0 = fmaxf(tm0, __shfl_xor_sync(0xffffffffu, tm0, 1));
        tm0 = fmaxf(tm0, __shfl_xor_sync(0xffffffffu, tm0, 2));
        tm1 = fmaxf(tm1, __shfl_xor_sync(0xffffffffu, tm1, 1));
        tm1 = fmaxf(tm1, __shfl_xor_sync(0xffffffffu, tm1, 2));

        float mn0 = fmaxf(mrun0, tm0), mn1 = fmaxf(mrun1, tm1);
        float a0 = __expf(mrun0 - mn0), a1 = __expf(mrun1 - mn1);
        mrun0 = mn0; mrun1 = mn1;

        float rs0 = 0.f, rs1 = 0.f;
        #pragma unroll
        for (int j = 0; j < 16; j++) {
            sacc[j][0] = __expf(sacc[j][0] - mn0);
            sacc[j][1] = __expf(sacc[j][1] - mn0);
            sacc[j][2] = __expf(sacc[j][2] - mn1);
            sacc[j][3] = __expf(sacc[j][3] - mn1);
            rs0 += sacc[j][0] + sacc[j][1];
            rs1 += sacc[j][2] + sacc[j][3];
        }
        rs0 += __shfl_xor_sync(0xffffffffu, rs0, 1);
        rs0 += __shfl_xor_sync(0xffffffffu, rs0, 2);
        rs1 += __shfl_xor_sync(0xffffffffu, rs1, 1);
        rs1 += __shfl_xor_sync(0xffffffffu, rs1, 2);
        l0 = l0 * a0 + rs0;
        l1 = l1 * a1 + rs1;

        #pragma unroll
        for (int n = 0; n < 8; n++) {
            oacc[n][0] *= a0; oacc[n][1] *= a0;
            oacc[n][2] *= a1; oacc[n][3] *= a1;
        }

        // O += P * V : permute P acc-layout -> A-frag layout via quad shfls
        #pragma unroll
        for (int j = 0; j < 16; j++) {
            uint32_t u0 = f2tf(sacc[j][0]), u1 = f2tf(sacc[j][1]);
            uint32_t u2 = f2tf(sacc[j][2]), u3 = f2tf(sacc[j][3]);
            uint32_t af[4];
            uint32_t x0 = __shfl_sync(0xffffffffu, u0, s0l);
            uint32_t x1 = __shfl_sync(0xffffffffu, u1, s0l);
            af[0] = odd ? x1 : x0;
            x0 = __shfl_sync(0xffffffffu, u2, s0l);
            x1 = __shfl_sync(0xffffffffu, u3, s0l);
            af[1] = odd ? x1 : x0;
            x0 = __shfl_sync(0xffffffffu, u0, s1l);
            x1 = __shfl_sync(0xffffffffu, u1, s1l);
            af[2] = odd ? x1 : x0;
            x0 = __shfl_sync(0xffffffffu, u2, s1l);
            x1 = __shfl_sync(0xffffffffu, u3, s1l);
            af[3] = odd ? x1 : x0;
            #pragma unroll
            for (int n = 0; n < 8; n++) {
                uint32_t bb[2] = { Vs[(8 * n + g) * VS_LD + 8 * j + t],
                                   Vs[(8 * n + g) * VS_LD + 8 * j + t + 4] };
                mma_tf32(oacc[n], af, bb);
            }
        }
    }

    // Epilogue: O /= l, scatter to ctx[b, s, h*64 + d]
    float i0 = 1.f / l0, i1 = 1.f / l1;
    float* cp = ctx + ((size_t)b * SS + q0 + w * 16) * (HH * DV) + h * DV;
    #pragma unroll
    for (int n = 0; n < 8; n++) {
        float2 v0 = make_float2(oacc[n][0] * i0, oacc[n][1] * i0);
        float2 v1 = make_float2(oacc[n][2] * i1, oacc[n][3] * i1);
        *reinterpret_cast<float2*>(&cp[(size_t)g * (HH * DV) + 8 * n + 2 * t]) = v0;
        *reinterpret_cast<float2*>(&cp[(size_t)(g + 8) * (HH * DV) + 8 * n + 2 * t]) = v1;
    }
}

extern "C" void kernel_launch(void* const* d_in, const int* in_sizes, int n_in,
                              void* d_out, int out_size) {
    const float* queries = (const float*)d_in[0];
    const float* keys    = (const float*)d_in[1];
    const float* values  = (const float*)d_in[2];
    const float* bias    = (const float*)d_in[3];
    const float* Wq      = (const float*)d_in[4];
    const float* Wk      = (const float*)d_in[5];
    const float* Wv      = (const float*)d_in[6];
    const float* Wp      = (const float*)d_in[7];
    float* out = (float*)d_out;

    float *q, *k, *vt, *ctx;
    cudaGetSymbolAddress((void**)&q,   g_q);
    cudaGetSymbolAddress((void**)&k,   g_k);
    cudaGetSymbolAddress((void**)&vt,  g_vt);
    cudaGetSymbolAddress((void**)&ctx, g_ctx);

    const int M = BB * SS; // 4096
    const int flash_smem = (128 * KS_LD + 64 * VS_LD) * 4; // 68608

    cudaFuncSetAttribute(flash_attn,
        cudaFuncAttributeMaxDynamicSharedMemorySize, flash_smem);

    // Projections: X[4096,1024] @ W[1024,1024]^T
    gemm_tf32<128,128,32,2,4,1><<<dim3(8, 32), 256>>>(queries, Wq, q,  M, 1024, 1024);
    gemm_tf32<128,128,32,2,4,1><<<dim3(8, 32), 256>>>(keys,    Wk, k,  M, 1024, 1024);
    gemm_tf32<128,128,32,2,4,2><<<dim3(8, 32), 256>>>(values,  Wv, vt, M, 1024, 1024);

    // Fused attention -> ctx
    flash_attn<<<dim3(8, BB * HH), 256, flash_smem>>>(q, k, vt, bias, ctx);

    // Output projection: ctx[4096,1024] @ Wp[1024,1024]^T
    gemm_tf32<128,128,32,2,4,0><<<dim3(8, 32), 256>>>(ctx, Wp, out, M, 1024, 1024);
}